// round 2
// baseline (speedup 1.0000x reference)
#include <cuda_runtime.h>
#include <cstdint>

#define N_TOK 32768
#define DDIM 256
#define KSTAGES 8
#define CDSZ 1024

#define TM 64
#define TN 128
#define TKC 32
#define AS_STRIDE 264
#define BS_STRIDE 132
#define NBLK (N_TOK / TM)                 // 512
#define SMEM_BYTES ((TM * AS_STRIDE + TKC * BS_STRIDE) * 4)  // 84480

// ------------------------- device scratch (no allocs) -------------------------
__device__ float g_res[N_TOK * DDIM];               // running residual (32 MB)
__device__ float g_cbT[KSTAGES * DDIM * CDSZ];      // d-major codebooks (8 MB)
__device__ float g_cnorm[KSTAGES * CDSZ];           // ||c||^2
__device__ float g_partials[KSTAGES * NBLK];        // per-block loss partials

typedef unsigned long long u64;

__device__ __forceinline__ u64 pack2(float x, float y) {
    u64 r; asm("mov.b64 %0, {%1, %2};" : "=l"(r) : "f"(x), "f"(y)); return r;
}
__device__ __forceinline__ float2 unpack2(u64 v) {
    float2 f; asm("mov.b64 {%0, %1}, %2;" : "=f"(f.x), "=f"(f.y) : "l"(v)); return f;
}
__device__ __forceinline__ u64 fma2(u64 a, u64 b, u64 c) {
    u64 d; asm("fma.rn.f32x2 %0, %1, %2, %3;" : "=l"(d) : "l"(a), "l"(b), "l"(c)); return d;
}

// ------------------------- prep: transpose + code norms -------------------------
__global__ void transpose_cb_kernel(const float* __restrict__ cb) {
    __shared__ float tile[32][33];
    int s = blockIdx.z;
    int d0 = blockIdx.x * 32, c0 = blockIdx.y * 32;
    int tx = threadIdx.x, ty = threadIdx.y;
    const float* src = cb + (size_t)s * CDSZ * DDIM;
    float* dst = g_cbT + (size_t)s * DDIM * CDSZ;
#pragma unroll
    for (int i = 0; i < 32; i += 8)
        tile[ty + i][tx] = src[(size_t)(c0 + ty + i) * DDIM + d0 + tx];
    __syncthreads();
#pragma unroll
    for (int i = 0; i < 32; i += 8)
        dst[(size_t)(d0 + ty + i) * CDSZ + c0 + tx] = tile[tx][ty + i];
}

// ||c||^2 in XLA:GPU row-reduction order: lane-strided fma, xor-butterfly.
__global__ void cnorm_kernel(const float* __restrict__ cb) {
    int row = blockIdx.x * 8 + (threadIdx.x >> 5);   // 0 .. 8191
    int lane = threadIdx.x & 31;
    const float* p = cb + (size_t)row * DDIM;
    float s = 0.f;
#pragma unroll
    for (int j = 0; j < 8; j++) { float v = p[lane + 32 * j]; s = fmaf(v, v, s); }
#pragma unroll
    for (int off = 16; off; off >>= 1) s += __shfl_xor_sync(0xffffffffu, s, off);
    if (lane == 0) g_cnorm[row] = s;
}

// ------------------------- per-stage fused GEMM+argmin+update -------------------------
extern __shared__ float smem_dyn[];

__global__ __launch_bounds__(128, 2) void rvq_stage_kernel(
    const float* __restrict__ x,     // residual source for stage 0
    const float* __restrict__ cb,    // this stage's codebook [CDSZ*DDIM], c-major
    int stage,
    float* __restrict__ encf)        // d_out + 2 (enc region, token-major)
{
    float* As = smem_dyn;                      // [TM][AS_STRIDE]
    float* Bs = smem_dyn + TM * AS_STRIDE;     // [TKC][BS_STRIDE]
    __shared__ float rnorm_s[TM];
    __shared__ int bestI_s[TM];
    __shared__ float wsum[4];

    const int tid = threadIdx.x;
    const int tx = tid & 15, ty = tid >> 4;
    const int tok0 = blockIdx.x * TM;
    const float* cbT = g_cbT + (size_t)stage * DDIM * CDSZ;
    const float* cnorm = g_cnorm + stage * CDSZ;
    const float* src = (stage == 0) ? x : g_res;

    // load 64x256 residual tile (float4, coalesced)
#pragma unroll
    for (int it = 0; it < 32; it++) {
        int idx4 = it * 128 + tid;
        int r = idx4 >> 6;
        int c4 = (idx4 & 63) << 2;
        float4 v = *(const float4*)&src[(size_t)(tok0 + r) * DDIM + c4];
        *(float4*)&As[r * AS_STRIDE + c4] = v;
    }
    __syncthreads();

    // rnorm per token, warp-per-row, lane-strided fma + butterfly (XLA:GPU order)
    {
        const int warpId = tid >> 5, lane = tid & 31;
        for (int t = warpId; t < TM; t += 4) {
            float s = 0.f;
#pragma unroll
            for (int j = 0; j < 8; j++) {
                float v = As[t * AS_STRIDE + lane + 32 * j];
                s = fmaf(v, v, s);
            }
#pragma unroll
            for (int off = 16; off; off >>= 1) s += __shfl_xor_sync(0xffffffffu, s, off);
            if (lane == 0) rnorm_s[t] = s;
        }
    }

    float bestVr[8];
    int bestIr[8];
#pragma unroll
    for (int i = 0; i < 8; i++) { bestVr[i] = 3.4e38f; bestIr[i] = 0; }

    for (int ct = 0; ct < CDSZ; ct += TN) {
        // pure dot accumulators, k ascending 0..255 (gemm order), fp32 fma per lane
        u64 acc[8][4];
#pragma unroll
        for (int i = 0; i < 8; i++)
#pragma unroll
            for (int j2 = 0; j2 < 4; j2++) acc[i][j2] = 0ull;

        for (int kk = 0; kk < DDIM; kk += TKC) {
            __syncthreads();
#pragma unroll
            for (int it = 0; it < 8; it++) {
                int idx4 = it * 128 + tid;
                int kr = idx4 >> 5;
                int c4 = (idx4 & 31) << 2;
                float4 v = *(const float4*)&cbT[(size_t)(kk + kr) * CDSZ + ct + c4];
                *(float4*)&Bs[kr * BS_STRIDE + c4] = v;
            }
            __syncthreads();
#pragma unroll
            for (int k = 0; k < TKC; k += 4) {
                float4 a4[8];
#pragma unroll
                for (int i = 0; i < 8; i++)
                    a4[i] = *(const float4*)&As[(ty * 8 + i) * AS_STRIDE + kk + k];
#pragma unroll
                for (int dk = 0; dk < 4; dk++) {
                    const u64* bp = (const u64*)&Bs[(k + dk) * BS_STRIDE + tx * 8];
                    u64 b0 = bp[0], b1 = bp[1], b2 = bp[2], b3 = bp[3];
#pragma unroll
                    for (int i = 0; i < 8; i++) {
                        float av = ((const float*)&a4[i])[dk];
                        u64 ap = pack2(av, av);
                        acc[i][0] = fma2(ap, b0, acc[i][0]);
                        acc[i][1] = fma2(ap, b1, acc[i][1]);
                        acc[i][2] = fma2(ap, b2, acc[i][2]);
                        acc[i][3] = fma2(ap, b3, acc[i][3]);
                    }
                }
            }
        }

        // d2 = (rnorm - 2*dot) + cnorm, explicit op order (no contraction),
        // then argmin with strict-< / lowest-index tie-break (jnp.argmin).
        float2 cnp[4];
#pragma unroll
        for (int j2 = 0; j2 < 4; j2++)
            cnp[j2] = *(const float2*)&cnorm[ct + tx * 8 + j2 * 2];

#pragma unroll
        for (int i = 0; i < 8; i++) {
            float R = rnorm_s[ty * 8 + i];
            float bv = 3.4e38f; int bi = 0;
#pragma unroll
            for (int j2 = 0; j2 < 4; j2++) {
                float2 f = unpack2(acc[i][j2]);
                int c0 = ct + tx * 8 + j2 * 2;
                float d2x = __fadd_rn(__fsub_rn(R, __fmul_rn(2.0f, f.x)), cnp[j2].x);
                float d2y = __fadd_rn(__fsub_rn(R, __fmul_rn(2.0f, f.y)), cnp[j2].y);
                if (d2x < bv) { bv = d2x; bi = c0; }
                if (d2y < bv) { bv = d2y; bi = c0 + 1; }
            }
#pragma unroll
            for (int off = 8; off; off >>= 1) {
                float ov = __shfl_xor_sync(0xffffffffu, bv, off);
                int oi = __shfl_xor_sync(0xffffffffu, bi, off);
                if (ov < bv || (ov == bv && oi < bi)) { bv = ov; bi = oi; }
            }
            if (bv < bestVr[i]) { bestVr[i] = bv; bestIr[i] = bi; }
        }
    }
    if (tx == 0) {
#pragma unroll
        for (int i = 0; i < 8; i++) bestI_s[ty * 8 + i] = bestIr[i];
    }
    __syncthreads();

    // residual update + deterministic loss partial + enc output
    const int warpId = tid >> 5, lane = tid & 31;
    float lsum = 0.f;
    for (int t = warpId; t < TM; t += 4) {
        int e = bestI_s[t];
        const float* crow = cb + (size_t)e * DDIM;
#pragma unroll
        for (int jj = 0; jj < 8; jj++) {
            int d = lane + jj * 32;
            float r = As[t * AS_STRIDE + d];
            float c = __ldg(&crow[d]);
            float nr = r - c;
            g_res[(size_t)(tok0 + t) * DDIM + d] = nr;
            lsum = fmaf(nr, nr, lsum);
        }
        if (lane == 0) encf[(size_t)(tok0 + t) * KSTAGES + stage] = (float)e;
    }
#pragma unroll
    for (int off = 16; off; off >>= 1) lsum += __shfl_xor_sync(0xffffffffu, lsum, off);
    if (lane == 0) wsum[warpId] = lsum;
    __syncthreads();
    if (tid == 0)
        g_partials[stage * NBLK + blockIdx.x] = wsum[0] + wsum[1] + wsum[2] + wsum[3];
}

// ------------------------- epilogue -------------------------
__global__ void finalize_kernel(float* __restrict__ out) {
    __shared__ float sh[256];
    int tid = threadIdx.x;
    float s = 0.f;
    for (int i = tid; i < KSTAGES * NBLK; i += 256) s += g_partials[i];
    sh[tid] = s;
    __syncthreads();
    for (int off = 128; off; off >>= 1) {
        if (tid < off) sh[tid] += sh[tid + off];
        __syncthreads();
    }
    if (tid == 0) {
        float loss = sh[0] * (1.0f / (float)((size_t)N_TOK * DDIM));
        out[0] = loss;   // loss_cd
        out[1] = loss;   // loss_enc (forward values identical)
    }
}

__global__ void quant_kernel(const float* __restrict__ x, float* __restrict__ out) {
    float* q = out + 2 + (size_t)N_TOK * KSTAGES;
    int i = blockIdx.x * blockDim.x + threadIdx.x;
    int stride = gridDim.x * blockDim.x;
    for (; i < N_TOK * DDIM; i += stride) q[i] = x[i] - g_res[i];
}

// ------------------------- launch -------------------------
extern "C" void kernel_launch(void* const* d_in, const int* in_sizes, int n_in,
                              void* d_out, int out_size) {
    const float* x  = (const float*)d_in[0];
    const float* cb = (const float*)d_in[1];
    if (n_in >= 2 && in_sizes[0] == KSTAGES * CDSZ * DDIM && in_sizes[1] == N_TOK * DDIM) {
        const float* t = x; x = cb; cb = t;
    }
    float* out = (float*)d_out;

    cudaFuncSetAttribute(rvq_stage_kernel,
                         cudaFuncAttributeMaxDynamicSharedMemorySize, SMEM_BYTES);

    transpose_cb_kernel<<<dim3(8, 32, 8), dim3(32, 8)>>>(cb);
    cnorm_kernel<<<(KSTAGES * CDSZ) / 8, 256>>>(cb);

    for (int s = 0; s < KSTAGES; s++) {
        rvq_stage_kernel<<<NBLK, 128, SMEM_BYTES>>>(
            x, cb + (size_t)s * CDSZ * DDIM, s, out + 2);
    }

    finalize_kernel<<<1, 256>>>(out);
    quant_kernel<<<4096, 256>>>(x, out);
}